// round 14
// baseline (speedup 1.0000x reference)
#include <cuda_runtime.h>
#include <cuda_bf16.h>
#include <math.h>
#include <stdint.h>

// ---------------- problem constants ----------------
#define NN_ 200
#define UU  64
#define BB  64
#define TT  12
#define LL  4
#define ROWS (NN_*BB)        // 12800
#define FMAX 264
#define CHUNK (ROWS*FMAX)
#define RHCH (ROWS*UU)

typedef unsigned short ush;

// ---------------- device scratch ----------------
__device__ ush g_Xh[3*CHUNK], g_Xl[3*CHUNK];      // [x0|x1|x2], ld=F
__device__ ush g_RHh[3*RHCH], g_RHl[3*RHCH];      // [rh | S rh | 2S^2 rh - rh]
__device__ ush g_h3h[ROWS*UU], g_h3l[ROWS*UU];
__device__ float g_U [ROWS*UU];
__device__ float g_H [LL*ROWS*UU];
__device__ float g_PROJ[BB*NN_*NN_];
__device__ float g_SS[400*200];
__device__ ush g_SSh[512*208], g_SSl[512*208];

#define GWSZ (128*800 + 3*128*384)
#define CWSZ (64*800 + 3*64*384)
#define PRSZ (256*64)
__device__ ush g_Bgh_e[GWSZ], g_Bgl_e[GWSZ], g_Bgh_d[GWSZ], g_Bgl_d[GWSZ];
__device__ ush g_Bch_e[CWSZ], g_Bcl_e[CWSZ], g_Bch_d[CWSZ], g_Bcl_d[CWSZ];
__device__ ush g_Bph[PRSZ], g_Bpl[PRSZ];

// ---------------- helpers ----------------
__device__ __forceinline__ uint32_t smem_u32(const void* p) {
    uint32_t a;
    asm("{ .reg .u64 t; cvta.to.shared.u64 t, %1; cvt.u32.u64 %0, t; }" : "=r"(a) : "l"(p));
    return a;
}
__device__ __forceinline__ void ldm_x4(uint32_t a, uint32_t& r0, uint32_t& r1,
                                       uint32_t& r2, uint32_t& r3) {
    asm volatile("ldmatrix.sync.aligned.m8n8.x4.shared.b16 {%0,%1,%2,%3}, [%4];"
                 : "=r"(r0), "=r"(r1), "=r"(r2), "=r"(r3) : "r"(a));
}
__device__ __forceinline__ void ldm_x2(uint32_t a, uint32_t& r0, uint32_t& r1) {
    asm volatile("ldmatrix.sync.aligned.m8n8.x2.shared.b16 {%0,%1}, [%2];"
                 : "=r"(r0), "=r"(r1) : "r"(a));
}
__device__ __forceinline__ void mma16816(float* c, const uint32_t* a, const uint32_t* b) {
    asm volatile("mma.sync.aligned.m16n8k16.row.col.f32.bf16.bf16.f32 "
                 "{%0,%1,%2,%3}, {%4,%5,%6,%7}, {%8,%9}, {%0,%1,%2,%3};"
                 : "+f"(c[0]), "+f"(c[1]), "+f"(c[2]), "+f"(c[3])
                 : "r"(a[0]), "r"(a[1]), "r"(a[2]), "r"(a[3]), "r"(b[0]), "r"(b[1]));
}
__device__ __forceinline__ void split_bf16(float v, ush& h, ush& l) {
    __nv_bfloat16 hb = __float2bfloat16(v);
    float hf = __bfloat162float(hb);
    __nv_bfloat16 lb = __float2bfloat16(v - hf);
    h = __bfloat16_as_ushort(hb);
    l = __bfloat16_as_ushort(lb);
}
__device__ __forceinline__ float us2f(ush u) {
    return __bfloat162float(__ushort_as_bfloat16(u));
}

// ---------------- small kernels ----------------
__global__ void zerok(float* p, int n) {
    int i = blockIdx.x * 256 + threadIdx.x;
    if (i < n) p[i] = 0.f;
}

// build X0 = [x | h] split, ld = F. st == nullptr -> h part is zero.
__global__ void build_cat(ush* __restrict__ dh, ush* __restrict__ dl,
                          const float* __restrict__ xsrc, int xmode, int t,
                          const float* __restrict__ st, int Fi) {
    int F = Fi + UU;
    int idx = blockIdx.x * 256 + threadIdx.x;
    if (idx >= ROWS * F) return;
    int row = idx / F;
    int f = idx - row * F;
    int n = row >> 6, b = row & 63;
    float v;
    if (f < Fi) {
        if (xmode == 0)      v = xsrc[((long)b * TT + t) * 40000 + (long)n * 200 + f];
        else if (xmode == 1) v = xsrc[(long)b * 40000 + (long)n * 200 + f];
        else if (xmode == 2) v = 0.f;
        else                 v = xsrc[row * UU + f];
    } else {
        v = st ? st[row * UU + (f - Fi)] : 0.f;
    }
    ush h, l;
    split_bf16(v, h, l);
    dh[idx] = h; dl[idx] = l;
}

// s2copy: out[0:40000) = S (copy), out[40000:80000) = 2*S@S
#define DBK 8
__global__ __launch_bounds__(256) void s2copy(const float* __restrict__ S,
                                              float* __restrict__ out) {
    // copy slice: 10 CTAs x 4000 floats
    int cid = blockIdx.y * 2 + blockIdx.x;
    for (int i = threadIdx.x; i < 4000; i += 256)
        out[cid * 4000 + i] = S[cid * 4000 + i];

    __shared__ float As[DBK][40];
    __shared__ float Bs[DBK][128];
    int tid = threadIdx.x;
    int tx = tid & 31, ty = tid >> 5;
    int n0 = blockIdx.x * 128;
    int m0 = blockIdx.y * 40;
    float acc[5][4];
#pragma unroll
    for (int i = 0; i < 5; i++)
#pragma unroll
        for (int j = 0; j < 4; j++) acc[i][j] = 0.f;
    for (int k0 = 0; k0 < 200; k0 += DBK) {
        __syncthreads();
        As[tid & 7][tid >> 3] = S[(m0 + (tid >> 3)) * 200 + k0 + (tid & 7)];
        if (tid < 64) As[tid & 7][(256 + tid) >> 3] = S[(m0 + ((256 + tid) >> 3)) * 200 + k0 + (tid & 7)];
        float4 b4 = make_float4(0.f, 0.f, 0.f, 0.f);
        int gn = n0 + tx * 4;
        if (gn < 200) {
            const float* p = &S[(k0 + ty) * 200 + gn];
            b4.x = p[0]; b4.y = (gn + 1 < 200) ? p[1] : 0.f;
            b4.z = (gn + 2 < 200) ? p[2] : 0.f; b4.w = (gn + 3 < 200) ? p[3] : 0.f;
        }
        *reinterpret_cast<float4*>(&Bs[ty][tx * 4]) = b4;
        __syncthreads();
#pragma unroll
        for (int kk = 0; kk < DBK; kk++) {
            float a[5], b[4];
#pragma unroll
            for (int i = 0; i < 5; i++) a[i] = As[kk][ty * 5 + i];
#pragma unroll
            for (int j = 0; j < 4; j++) b[j] = Bs[kk][tx * 4 + j];
#pragma unroll
            for (int i = 0; i < 5; i++)
#pragma unroll
                for (int j = 0; j < 4; j++) acc[i][j] += a[i] * b[j];
        }
    }
#pragma unroll
    for (int i = 0; i < 5; i++) {
        int gm = m0 + ty * 5 + i;
#pragma unroll
        for (int j = 0; j < 4; j++) {
            int gn = n0 + tx * 4 + j;
            if (gm < 200 && gn < 200) out[40000 + gm * 200 + gn] = 2.f * acc[i][j];
        }
    }
}

__global__ void ssplit(const float* __restrict__ SS,
                       ush* __restrict__ dh, ush* __restrict__ dl) {
    int idx = blockIdx.x * 256 + threadIdx.x;
    if (idx >= 512 * 208) return;
    int m = idx / 208, k = idx - m * 208;
    float v = (m < 400 && k < 200) ? SS[m * 200 + k] : 0.f;
    ush h, l;
    split_bf16(v, h, l);
    dh[idx] = h; dl[idx] = l;
}

__global__ void wsplitT(const float* __restrict__ src, int ldsrc, int Fw,
                        int Kpad, int Nsrc,
                        ush* __restrict__ dh, ush* __restrict__ dl) {
    int idx = blockIdx.x * 256 + threadIdx.x;
    if (idx >= Nsrc * Kpad) return;
    int n = idx / Kpad;
    int r = idx - n * Kpad;
    float v = 0.f;
    if (r < 3 * Fw) {
        int kb = r / Fw, f = r - kb * Fw;
        v = src[((long)f * 3 + kb) * ldsrc + n];
    }
    ush h, l;
    split_bf16(v, h, l);
    dh[idx] = h; dl[idx] = l;
}
__global__ void wsplit_cand(const float* __restrict__ src, int Fi, int Kpad,
                            ush* __restrict__ dh, ush* __restrict__ dl) {
    int idx = blockIdx.x * 256 + threadIdx.x;
    if (idx >= 64 * Kpad) return;
    int n = idx / Kpad;
    int k = idx - n * Kpad;
    float v = 0.f;
    if (k < 3 * Fi) {
        int kb = k / Fi, f = k - kb * Fi;
        v = src[((long)f * 3 + kb) * 64 + n];
    } else if (k < 3 * Fi + 192) {
        int kp = k - 3 * Fi;
        int kb = kp >> 6, u = kp & 63;
        v = src[((long)(Fi + u) * 3 + kb) * 64 + n];
    }
    ush h, l;
    split_bf16(v, h, l);
    dh[idx] = h; dl[idx] = l;
}
__global__ void wsplit_proj(const float* __restrict__ src,
                            ush* __restrict__ dh, ush* __restrict__ dl) {
    int idx = blockIdx.x * 256 + threadIdx.x;
    if (idx >= 256 * 64) return;
    int n = idx >> 6, k = idx & 63;
    float v = (n < 200) ? src[k * 200 + n] : 0.f;
    ush h, l;
    split_bf16(v, h, l);
    dh[idx] = h; dl[idx] = l;
}

#define ALD 24
#define BLD 24

// ---------------- mma diffusion kernel (8 warps, 32x32 warp tile) --------
__global__ __launch_bounds__(256) void diffmma(
    const ush* __restrict__ SSh, const ush* __restrict__ SSl,
    const ush* __restrict__ X0h, const ush* __restrict__ X0l, int ldx,
    ush* __restrict__ X1h, ush* __restrict__ X1l,
    ush* __restrict__ X2h, ush* __restrict__ X2l)
{
    __shared__ __align__(16) ush Ah[2][128][ALD], Al[2][128][ALD];
    __shared__ __align__(16) ush Bh[2][64][BLD], Bl[2][64][BLD];
    int tid = threadIdx.x, wid = tid >> 5, lane = tid & 31;
    int wm = wid >> 1, wn = wid & 1;
    int m0 = blockIdx.y * 128, n0 = blockIdx.x * 64;

    float acc[2][4][4];
#pragma unroll
    for (int i = 0; i < 2; i++)
#pragma unroll
        for (int j = 0; j < 4; j++)
#pragma unroll
            for (int q = 0; q < 4; q++) acc[i][j][q] = 0.f;

    uint32_t sAh = smem_u32(Ah), sAl = smem_u32(Al);
    uint32_t sBh = smem_u32(Bh), sBl = smem_u32(Bl);
    int lr = (lane & 7) + ((lane >> 3) & 1) * 8;
    int lc = (lane >> 4) * 8;
    int br7 = lane & 7, bsel = (lane >> 3) & 1;

    int ar = tid >> 1, ak8 = (tid & 1) * 8;
    int bk = tid >> 4, bn4 = (tid & 15) * 4;

    uint4 rah, ral; uint2 rbh2, rbl2;
    auto fetch = [&](int k0) {
        rah = *reinterpret_cast<const uint4*>(SSh + (long)(m0 + ar) * 208 + k0 + ak8);
        ral = *reinterpret_cast<const uint4*>(SSl + (long)(m0 + ar) * 208 + k0 + ak8);
        int k = k0 + bk;
        if (k < 200) {
            long off = (long)k * ldx + n0 + bn4;
            rbh2 = *reinterpret_cast<const uint2*>(X0h + off);
            rbl2 = *reinterpret_cast<const uint2*>(X0l + off);
        } else {
            rbh2 = make_uint2(0, 0); rbl2 = make_uint2(0, 0);
        }
    };
    auto store = [&](int buf) {
        *reinterpret_cast<uint4*>(&Ah[buf][ar][ak8]) = rah;
        *reinterpret_cast<uint4*>(&Al[buf][ar][ak8]) = ral;
        ush hs[4], ls[4];
        *reinterpret_cast<uint2*>(hs) = rbh2;
        *reinterpret_cast<uint2*>(ls) = rbl2;
#pragma unroll
        for (int j = 0; j < 4; j++) {
            Bh[buf][bn4 + j][bk] = hs[j];
            Bl[buf][bn4 + j][bk] = ls[j];
        }
    };

    fetch(0); store(0); __syncthreads();
    const int nk = 13;
    for (int kt = 0; kt < nk; kt++) {
        int cur = kt & 1;
        if (kt + 1 < nk) fetch((kt + 1) * 16);
        uint32_t ah[2][4], al[2][4], bh[4][2], bl[4][2];
#pragma unroll
        for (int mi = 0; mi < 2; mi++) {
            uint32_t off = (uint32_t)(((cur * 128 + wm * 32 + mi * 16 + lr) * ALD + lc) * 2);
            ldm_x4(sAh + off, ah[mi][0], ah[mi][1], ah[mi][2], ah[mi][3]);
            ldm_x4(sAl + off, al[mi][0], al[mi][1], al[mi][2], al[mi][3]);
        }
#pragma unroll
        for (int nf = 0; nf < 4; nf++) {
            uint32_t off = (uint32_t)(((cur * 64 + wn * 32 + nf * 8 + br7) * BLD + bsel * 8) * 2);
            ldm_x2(sBh + off, bh[nf][0], bh[nf][1]);
            ldm_x2(sBl + off, bl[nf][0], bl[nf][1]);
        }
#pragma unroll
        for (int mi = 0; mi < 2; mi++)
#pragma unroll
            for (int nf = 0; nf < 4; nf++) {
                mma16816(acc[mi][nf], ah[mi], bh[nf]);
                mma16816(acc[mi][nf], al[mi], bh[nf]);
                mma16816(acc[mi][nf], ah[mi], bl[nf]);
            }
        if (kt + 1 < nk) { store(cur ^ 1); __syncthreads(); }
    }

    int g = lane >> 2, tq = lane & 3;
#pragma unroll
    for (int mi = 0; mi < 2; mi++) {
#pragma unroll
        for (int nf = 0; nf < 4; nf++) {
            int cn = n0 + wn * 32 + nf * 8 + 2 * tq;
#pragma unroll
            for (int e = 0; e < 4; e++) {
                int gm = m0 + wm * 32 + mi * 16 + g + (e >> 1) * 8;
                int cc = cn + (e & 1);
                float v = acc[mi][nf][e];
                ush h, l;
                if (gm < 200) {
                    long p = (long)gm * ldx + cc;
                    split_bf16(v, h, l);
                    X1h[p] = h; X1l[p] = l;
                } else if (gm < 400) {
                    long p = (long)(gm - 200) * ldx + cc;
                    float x0 = us2f(X0h[p]) + us2f(X0l[p]);
                    split_bf16(v - x0, h, l);
                    X2h[p] = h; X2l[p] = l;
                }
            }
        }
    }
}

// ---------------- mma feature GEMM (8 warps, 32x32 warp tile) ------------
template<int MODE>
__device__ __forceinline__ void epi(float v, int gm, int cn,
    const float* bias, const float* H, const float* Uin,
    float* Of1, float* Of2, ush* Oh, ush* Ol, int t)
{
    if (MODE == 2) {
        float s = 1.f / (1.f + expf(-(v + bias[cn])));
        if (cn < UU) {
            ush h, l;
            split_bf16(s * H[gm * UU + cn], h, l);
            Oh[gm * UU + cn] = h; Ol[gm * UU + cn] = l;
        } else {
            Of1[gm * UU + cn - UU] = s;
        }
    } else if (MODE == 3) {
        float c = tanhf(v + bias[cn]);
        float u = Uin[gm * UU + cn];
        float hn = u * H[gm * UU + cn] + (1.f - u) * c;
        Of1[gm * UU + cn] = hn;
        if (Oh) {
            ush h, l;
            split_bf16(hn, h, l);
            Oh[gm * UU + cn] = h; Ol[gm * UU + cn] = l;
        }
    } else if (MODE == 4) {
        if (cn < 200) {
            float p = v + bias[cn];
            int b_ = gm & 63, n_ = gm >> 6;
            Of1[((long)b_ * TT + t) * 40000 + (long)n_ * 200 + cn] = p;
            Of2[(long)b_ * 40000 + (long)n_ * 200 + cn] = p;
        }
    }
}

template<int MODE>
__global__ __launch_bounds__(256) void featmma(
    const ush* __restrict__ A1h, const ush* __restrict__ A1l,
    int lda1, int Fb1, long ch1, int KA,
    const ush* __restrict__ A2h, const ush* __restrict__ A2l, long ch2,
    int K,
    const ush* __restrict__ Bwh, const ush* __restrict__ Bwl, int Kpad, int Nn,
    const float* __restrict__ bias, const float* __restrict__ H,
    const float* __restrict__ Uin,
    float* __restrict__ Of1, float* __restrict__ Of2,
    ush* __restrict__ Oh, ush* __restrict__ Ol, int t)
{
    __shared__ __align__(16) ush Ah[2][128][ALD], Al[2][128][ALD];
    __shared__ __align__(16) ush Bh[2][64][BLD], Bl[2][64][BLD];
    int tid = threadIdx.x, wid = tid >> 5, lane = tid & 31;
    int wm = wid >> 1, wn = wid & 1;
    int m0 = blockIdx.y * 128, n0 = blockIdx.x * 64;

    float acc[2][4][4];
#pragma unroll
    for (int i = 0; i < 2; i++)
#pragma unroll
        for (int j = 0; j < 4; j++)
#pragma unroll
            for (int q = 0; q < 4; q++) acc[i][j][q] = 0.f;

    uint32_t sAh = smem_u32(Ah), sAl = smem_u32(Al);
    uint32_t sBh = smem_u32(Bh), sBl = smem_u32(Bl);
    int lr = (lane & 7) + ((lane >> 3) & 1) * 8;
    int lc = (lane >> 4) * 8;
    int br7 = lane & 7, bsel = (lane >> 3) & 1;

    int ar = tid >> 1, ak8 = (tid & 1) * 8;
    int bn = tid >> 2, bk4 = (tid & 3) * 4;

    uint4 rah, ral; uint2 rbh, rbl;
    auto fetch = [&](int k0) {
        int k8 = k0 + ak8;
        if (k8 < K) {
            long off;
            if (k8 < KA) {
                int kb = k8 / Fb1, krel = k8 - kb * Fb1;
                off = (long)kb * ch1 + (long)(m0 + ar) * lda1 + krel;
                rah = *reinterpret_cast<const uint4*>(A1h + off);
                ral = *reinterpret_cast<const uint4*>(A1l + off);
            } else {
                int kp = k8 - KA;
                int kb = kp >> 6, krel = kp & 63;
                off = (long)kb * ch2 + (long)(m0 + ar) * 64 + krel;
                rah = *reinterpret_cast<const uint4*>(A2h + off);
                ral = *reinterpret_cast<const uint4*>(A2l + off);
            }
        } else {
            rah = make_uint4(0, 0, 0, 0);
            ral = make_uint4(0, 0, 0, 0);
        }
        long boff = (long)(n0 + bn) * Kpad + k0 + bk4;
        rbh = *reinterpret_cast<const uint2*>(Bwh + boff);
        rbl = *reinterpret_cast<const uint2*>(Bwl + boff);
    };
    auto store = [&](int buf) {
        *reinterpret_cast<uint4*>(&Ah[buf][ar][ak8]) = rah;
        *reinterpret_cast<uint4*>(&Al[buf][ar][ak8]) = ral;
        *reinterpret_cast<uint2*>(&Bh[buf][bn][bk4]) = rbh;
        *reinterpret_cast<uint2*>(&Bl[buf][bn][bk4]) = rbl;
    };

    int nk = (K + 15) / 16;
    fetch(0); store(0); __syncthreads();
    for (int kt = 0; kt < nk; kt++) {
        int cur = kt & 1;
        if (kt + 1 < nk) fetch((kt + 1) * 16);
        uint32_t ah[2][4], al[2][4], bh[4][2], bl[4][2];
#pragma unroll
        for (int mi = 0; mi < 2; mi++) {
            uint32_t off = (uint32_t)(((cur * 128 + wm * 32 + mi * 16 + lr) * ALD + lc) * 2);
            ldm_x4(sAh + off, ah[mi][0], ah[mi][1], ah[mi][2], ah[mi][3]);
            ldm_x4(sAl + off, al[mi][0], al[mi][1], al[mi][2], al[mi][3]);
        }
#pragma unroll
        for (int nf = 0; nf < 4; nf++) {
            uint32_t off = (uint32_t)(((cur * 64 + wn * 32 + nf * 8 + br7) * BLD + bsel * 8) * 2);
            ldm_x2(sBh + off, bh[nf][0], bh[nf][1]);
            ldm_x2(sBl + off, bl[nf][0], bl[nf][1]);
        }
#pragma unroll
        for (int mi = 0; mi < 2; mi++)
#pragma unroll
            for (int nf = 0; nf < 4; nf++) {
                mma16816(acc[mi][nf], ah[mi], bh[nf]);
                mma16816(acc[mi][nf], al[mi], bh[nf]);
                mma16816(acc[mi][nf], ah[mi], bl[nf]);
            }
        if (kt + 1 < nk) { store(cur ^ 1); __syncthreads(); }
    }

    int g = lane >> 2, tq = lane & 3;
#pragma unroll
    for (int mi = 0; mi < 2; mi++)
#pragma unroll
        for (int nf = 0; nf < 4; nf++) {
            int cn = n0 + wn * 32 + nf * 8 + 2 * tq;
#pragma unroll
            for (int e = 0; e < 4; e++) {
                int gm = m0 + wm * 32 + mi * 16 + g + (e >> 1) * 8;
                int cc = cn + (e & 1);
                if (cc < Nn)
                    epi<MODE>(acc[mi][nf][e], gm, cc, bias, H, Uin, Of1, Of2, Oh, Ol, t);
            }
        }
}

// ---------------- host orchestration ----------------
extern "C" void kernel_launch(void* const* d_in, const int* in_sizes, int n_in,
                              void* d_out, int out_size) {
    (void)in_sizes; (void)n_in; (void)out_size;
    const float* inputs  = (const float*)d_in[0];
    const float* Ssup    = (const float*)d_in[1];
    const float* enc_Wg0 = (const float*)d_in[2];
    const float* enc_bg0 = (const float*)d_in[3];
    const float* enc_Wc0 = (const float*)d_in[4];
    const float* enc_bc0 = (const float*)d_in[5];
    const float* enc_Wg  = (const float*)d_in[6];
    const float* enc_bg  = (const float*)d_in[7];
    const float* enc_Wc  = (const float*)d_in[8];
    const float* enc_bc  = (const float*)d_in[9];
    const float* dec_Wg0 = (const float*)d_in[10];
    const float* dec_bg0 = (const float*)d_in[11];
    const float* dec_Wc0 = (const float*)d_in[12];
    const float* dec_bc0 = (const float*)d_in[13];
    const float* dec_Wg  = (const float*)d_in[14];
    const float* dec_bg  = (const float*)d_in[15];
    const float* dec_Wc  = (const float*)d_in[16];
    const float* dec_bc  = (const float*)d_in[17];
    const float* proj_W  = (const float*)d_in[18];
    const float* proj_b  = (const float*)d_in[19];
    float* out = (float*)d_out;

    float *pU, *pH, *pPROJ, *pSS;
    cudaGetSymbolAddress((void**)&pU,    g_U);
    cudaGetSymbolAddress((void**)&pH,    g_H);
    cudaGetSymbolAddress((void**)&pPROJ, g_PROJ);
    cudaGetSymbolAddress((void**)&pSS,   g_SS);
    ush *pXh, *pXl, *pRHh, *pRHl, *ph3h, *ph3l, *pSSh, *pSSl, *pBph, *pBpl;
    cudaGetSymbolAddress((void**)&pXh,  g_Xh);
    cudaGetSymbolAddress((void**)&pXl,  g_Xl);
    cudaGetSymbolAddress((void**)&pRHh, g_RHh);
    cudaGetSymbolAddress((void**)&pRHl, g_RHl);
    cudaGetSymbolAddress((void**)&ph3h, g_h3h);
    cudaGetSymbolAddress((void**)&ph3l, g_h3l);
    cudaGetSymbolAddress((void**)&pSSh, g_SSh);
    cudaGetSymbolAddress((void**)&pSSl, g_SSl);
    cudaGetSymbolAddress((void**)&pBph, g_Bph);
    cudaGetSymbolAddress((void**)&pBpl, g_Bpl);
    ush *pBgh[2], *pBgl[2], *pBch[2], *pBcl[2];
    cudaGetSymbolAddress((void**)&pBgh[0], g_Bgh_e);
    cudaGetSymbolAddress((void**)&pBgl[0], g_Bgl_e);
    cudaGetSymbolAddress((void**)&pBgh[1], g_Bgh_d);
    cudaGetSymbolAddress((void**)&pBgl[1], g_Bgl_d);
    cudaGetSymbolAddress((void**)&pBch[0], g_Bch_e);
    cudaGetSymbolAddress((void**)&pBcl[0], g_Bcl_e);
    cudaGetSymbolAddress((void**)&pBch[1], g_Bch_d);
    cudaGetSymbolAddress((void**)&pBcl[1], g_Bcl_d);

    // ---- prep, ordered so launch index 3 == first diffmma (for ncu) ----
    s2copy<<<dim3(2, 5), 256>>>(Ssup, pSS);                                  // 0
    ssplit<<<(512 * 208 + 255) / 256, 256>>>(pSS, pSSh, pSSl);               // 1
    build_cat<<<(ROWS * 264) / 256, 256>>>(pXh, pXl, inputs, 0, 0,           // 2
                                           nullptr, 200);
    diffmma<<<dim3(264, 4), 256>>>(pSSh, pSSl, pXh, pXl, 64 * 264,           // 3 <- profiled
        pXh + CHUNK, pXl + CHUNK, pXh + 2 * CHUNK, pXl + 2 * CHUNK);
    zerok<<<(LL * ROWS * UU) / 256, 256>>>(pH, LL * ROWS * UU);              // 4

    // ---- weight splits ----
    const float* Wg0s[2] = {enc_Wg0, dec_Wg0};
    const float* Wgs[2]  = {enc_Wg,  dec_Wg};
    const float* Wc0s[2] = {enc_Wc0, dec_Wc0};
    const float* Wcs[2]  = {enc_Wc,  dec_Wc};
    for (int s = 0; s < 2; s++) {
        wsplitT<<<(128 * 800 + 255) / 256, 256>>>(Wg0s[s], 128, 264, 800, 128,
                                                  pBgh[s], pBgl[s]);
        wsplit_cand<<<(64 * 800 + 255) / 256, 256>>>(Wc0s[s], 200, 800,
                                                     pBch[s], pBcl[s]);
        for (int i = 0; i < 3; i++) {
            wsplitT<<<(128 * 384 + 255) / 256, 256>>>(Wgs[s] + (long)i * 384 * 128, 128,
                128, 384, 128,
                pBgh[s] + 128 * 800 + (long)i * 128 * 384,
                pBgl[s] + 128 * 800 + (long)i * 128 * 384);
            wsplit_cand<<<(64 * 384 + 255) / 256, 256>>>(Wcs[s] + (long)i * 384 * 64, 64, 384,
                pBch[s] + 64 * 800 + (long)i * 64 * 384,
                pBcl[s] + 64 * 800 + (long)i * 64 * 384);
        }
    }
    wsplit_proj<<<64, 256>>>(proj_W, pBph, pBpl);

    ush* RHD1h = pRHh + RHCH; ush* RHD1l = pRHl + RHCH;
    ush* RHD2h = pRHh + 2 * RHCH; ush* RHD2l = pRHl + 2 * RHCH;

    // ---- sequence loop ----
    for (int tg = 0; tg < 2 * TT; tg++) {
        bool enc = (tg < TT);
        int side = enc ? 0 : 1;
        int t = enc ? tg : (tg - TT);

        for (int l = 0; l < LL; l++) {
            int Fi = (l == 0) ? 200 : 64;
            int F = Fi + UU;
            int BF = BB * F;
            float* hl = pH + (long)l * ROWS * UU;

            const ush* Bgh = pBgh[side] + ((l == 0) ? 0 : 128 * 800 + (long)(l - 1) * 128 * 384);
            const ush* Bgl = pBgl[side] + ((l == 0) ? 0 : 128 * 800 + (long)(l - 1) * 128 * 384);
            int Kpg = (l == 0) ? 800 : 384;
            const ush* Bch = pBch[side] + ((l == 0) ? 0 : 64 * 800 + (long)(l - 1) * 64 * 384);
            const ush* Bcl = pBcl[side] + ((l == 0) ? 0 : 64 * 800 + (long)(l - 1) * 64 * 384);
            const float* bg = enc ? ((l == 0) ? enc_bg0 : enc_bg + (l - 1) * 128)
                                  : ((l == 0) ? dec_bg0 : dec_bg + (l - 1) * 128);
            const float* bc = enc ? ((l == 0) ? enc_bc0 : enc_bc + (l - 1) * 64)
                                  : ((l == 0) ? dec_bc0 : dec_bc + (l - 1) * 64);

            int xmode;
            const float* xsrc;
            if (l > 0)       { xmode = 3; xsrc = pH + (long)(l - 1) * ROWS * UU; }
            else if (enc)    { xmode = 0; xsrc = inputs; }
            else if (t == 0) { xmode = 2; xsrc = pPROJ; }
            else             { xmode = 1; xsrc = pPROJ; }

            if (!(tg == 0 && l == 0)) {  // first cell's build+diff issued in prep
                build_cat<<<(ROWS * F) / 256, 256>>>(pXh, pXl, xsrc, xmode, t, hl, Fi);
                diffmma<<<dim3(BF / 64, 4), 256>>>(pSSh, pSSl, pXh, pXl, BF,
                    pXh + CHUNK, pXl + CHUNK, pXh + 2 * CHUNK, pXl + 2 * CHUNK);
            }
            // gates
            featmma<2><<<dim3(2, 100), 256>>>(pXh, pXl, F, F, (long)CHUNK, 3 * F,
                nullptr, nullptr, 0, 3 * F, Bgh, Bgl, Kpg, 128,
                bg, hl, nullptr, pU, nullptr, pRHh, pRHl, 0);
            // rh diffusion
            diffmma<<<dim3(64, 4), 256>>>(pSSh, pSSl, pRHh, pRHl, 4096,
                RHD1h, RHD1l, RHD2h, RHD2l);
            // candidate (fused x + h parts) + GRU update
            featmma<3><<<dim3(1, 100), 256>>>(pXh, pXl, F, Fi, (long)CHUNK, 3 * Fi,
                pRHh, pRHl, (long)RHCH, 3 * Fi + 192, Bch, Bcl, Kpg, 64,
                bc, hl, pU, hl, nullptr,
                (l == 3) ? ph3h : nullptr, (l == 3) ? ph3l : nullptr, 0);
        }

        if (!enc) {
            featmma<4><<<dim3(4, 100), 256>>>(ph3h, ph3l, 64, 64, 0, 64,
                nullptr, nullptr, 0, 64, pBph, pBpl, 64, 200,
                proj_b, nullptr, nullptr, out, pPROJ, nullptr, nullptr, t);
        }
    }
}

// round 15
// speedup vs baseline: 1.7087x; 1.7087x over previous
#include <cuda_runtime.h>
#include <cuda_bf16.h>
#include <math.h>
#include <stdint.h>

// ---------------- problem constants ----------------
#define NN_ 200
#define UU  64
#define BB  64
#define TT  12
#define LL  4
#define ROWS (NN_*BB)        // 12800
#define FMAX 264
#define CHUNK (ROWS*FMAX)
#define RHCH (ROWS*UU)

typedef unsigned short ush;

// ---------------- device scratch ----------------
__device__ ush g_Xh[3*CHUNK], g_Xl[3*CHUNK];      // [x0|x1|x2], ld=F
__device__ ush g_RHh[3*RHCH], g_RHl[3*RHCH];      // [rh | S rh | 2S^2 rh - rh]
__device__ ush g_h3h[ROWS*UU], g_h3l[ROWS*UU];
__device__ float g_U [ROWS*UU];
__device__ float g_H [LL*ROWS*UU];
__device__ float g_PROJ[BB*NN_*NN_];
__device__ float g_SS[400*200];
__device__ ush g_SSh[512*208], g_SSl[512*208];

#define GWSZ (128*800 + 3*128*384)
#define CWSZ (64*800 + 3*64*384)
#define PRSZ (256*64)
__device__ ush g_Bgh_e[GWSZ], g_Bgl_e[GWSZ], g_Bgh_d[GWSZ], g_Bgl_d[GWSZ];
__device__ ush g_Bch_e[CWSZ], g_Bcl_e[CWSZ], g_Bch_d[CWSZ], g_Bcl_d[CWSZ];
__device__ ush g_Bph[PRSZ], g_Bpl[PRSZ];

// ---------------- helpers ----------------
__device__ __forceinline__ uint32_t smem_u32(const void* p) {
    uint32_t a;
    asm("{ .reg .u64 t; cvta.to.shared.u64 t, %1; cvt.u32.u64 %0, t; }" : "=r"(a) : "l"(p));
    return a;
}
__device__ __forceinline__ void ldm_x4(uint32_t a, uint32_t& r0, uint32_t& r1,
                                       uint32_t& r2, uint32_t& r3) {
    asm volatile("ldmatrix.sync.aligned.m8n8.x4.shared.b16 {%0,%1,%2,%3}, [%4];"
                 : "=r"(r0), "=r"(r1), "=r"(r2), "=r"(r3) : "r"(a));
}
__device__ __forceinline__ void ldm_x4t(uint32_t a, uint32_t& r0, uint32_t& r1,
                                        uint32_t& r2, uint32_t& r3) {
    asm volatile("ldmatrix.sync.aligned.m8n8.x4.trans.shared.b16 {%0,%1,%2,%3}, [%4];"
                 : "=r"(r0), "=r"(r1), "=r"(r2), "=r"(r3) : "r"(a));
}
__device__ __forceinline__ void mma16816(float* c, const uint32_t* a, const uint32_t* b) {
    asm volatile("mma.sync.aligned.m16n8k16.row.col.f32.bf16.bf16.f32 "
                 "{%0,%1,%2,%3}, {%4,%5,%6,%7}, {%8,%9}, {%0,%1,%2,%3};"
                 : "+f"(c[0]), "+f"(c[1]), "+f"(c[2]), "+f"(c[3])
                 : "r"(a[0]), "r"(a[1]), "r"(a[2]), "r"(a[3]), "r"(b[0]), "r"(b[1]));
}
__device__ __forceinline__ void split_bf16(float v, ush& h, ush& l) {
    __nv_bfloat16 hb = __float2bfloat16(v);
    float hf = __bfloat162float(hb);
    __nv_bfloat16 lb = __float2bfloat16(v - hf);
    h = __bfloat16_as_ushort(hb);
    l = __bfloat16_as_ushort(lb);
}
__device__ __forceinline__ float us2f(ush u) {
    return __bfloat162float(__ushort_as_bfloat16(u));
}

// ---------------- small kernels ----------------
__global__ void zerok(float* p, int n) {
    int i = blockIdx.x * 256 + threadIdx.x;
    if (i < n) p[i] = 0.f;
}

// build X0 = [x | h] split, ld = F. st == nullptr -> h part is zero.
__global__ void build_cat(ush* __restrict__ dh, ush* __restrict__ dl,
                          const float* __restrict__ xsrc, int xmode, int t,
                          const float* __restrict__ st, int Fi) {
    int F = Fi + UU;
    int idx = blockIdx.x * 256 + threadIdx.x;
    if (idx >= ROWS * F) return;
    int row = idx / F;
    int f = idx - row * F;
    int n = row >> 6, b = row & 63;
    float v;
    if (f < Fi) {
        if (xmode == 0)      v = xsrc[((long)b * TT + t) * 40000 + (long)n * 200 + f];
        else if (xmode == 1) v = xsrc[(long)b * 40000 + (long)n * 200 + f];
        else if (xmode == 2) v = 0.f;
        else                 v = xsrc[row * UU + f];
    } else {
        v = st ? st[row * UU + (f - Fi)] : 0.f;
    }
    ush h, l;
    split_bf16(v, h, l);
    dh[idx] = h; dl[idx] = l;
}

// s2copy: out[0:40000) = S (copy), out[40000:80000) = 2*S@S
#define DBK 8
__global__ __launch_bounds__(256) void s2copy(const float* __restrict__ S,
                                              float* __restrict__ out) {
    int cid = blockIdx.y * 2 + blockIdx.x;
    for (int i = threadIdx.x; i < 4000; i += 256)
        out[cid * 4000 + i] = S[cid * 4000 + i];

    __shared__ float As[DBK][40];
    __shared__ float Bs[DBK][128];
    int tid = threadIdx.x;
    int tx = tid & 31, ty = tid >> 5;
    int n0 = blockIdx.x * 128;
    int m0 = blockIdx.y * 40;
    float acc[5][4];
#pragma unroll
    for (int i = 0; i < 5; i++)
#pragma unroll
        for (int j = 0; j < 4; j++) acc[i][j] = 0.f;
    for (int k0 = 0; k0 < 200; k0 += DBK) {
        __syncthreads();
        As[tid & 7][tid >> 3] = S[(m0 + (tid >> 3)) * 200 + k0 + (tid & 7)];
        if (tid < 64) As[tid & 7][(256 + tid) >> 3] = S[(m0 + ((256 + tid) >> 3)) * 200 + k0 + (tid & 7)];
        float4 b4 = make_float4(0.f, 0.f, 0.f, 0.f);
        int gn = n0 + tx * 4;
        if (gn < 200) {
            const float* p = &S[(k0 + ty) * 200 + gn];
            b4.x = p[0]; b4.y = (gn + 1 < 200) ? p[1] : 0.f;
            b4.z = (gn + 2 < 200) ? p[2] : 0.f; b4.w = (gn + 3 < 200) ? p[3] : 0.f;
        }
        *reinterpret_cast<float4*>(&Bs[ty][tx * 4]) = b4;
        __syncthreads();
#pragma unroll
        for (int kk = 0; kk < DBK; kk++) {
            float a[5], b[4];
#pragma unroll
            for (int i = 0; i < 5; i++) a[i] = As[kk][ty * 5 + i];
#pragma unroll
            for (int j = 0; j < 4; j++) b[j] = Bs[kk][tx * 4 + j];
#pragma unroll
            for (int i = 0; i < 5; i++)
#pragma unroll
                for (int j = 0; j < 4; j++) acc[i][j] += a[i] * b[j];
        }
    }
#pragma unroll
    for (int i = 0; i < 5; i++) {
        int gm = m0 + ty * 5 + i;
#pragma unroll
        for (int j = 0; j < 4; j++) {
            int gn = n0 + tx * 4 + j;
            if (gm < 200 && gn < 200) out[40000 + gm * 200 + gn] = 2.f * acc[i][j];
        }
    }
}

__global__ void ssplit(const float* __restrict__ SS,
                       ush* __restrict__ dh, ush* __restrict__ dl) {
    int idx = blockIdx.x * 256 + threadIdx.x;
    if (idx >= 512 * 208) return;
    int m = idx / 208, k = idx - m * 208;
    float v = (m < 400 && k < 200) ? SS[m * 200 + k] : 0.f;
    ush h, l;
    split_bf16(v, h, l);
    dh[idx] = h; dl[idx] = l;
}

__global__ void wsplitT(const float* __restrict__ src, int ldsrc, int Fw,
                        int Kpad, int Nsrc,
                        ush* __restrict__ dh, ush* __restrict__ dl) {
    int idx = blockIdx.x * 256 + threadIdx.x;
    if (idx >= Nsrc * Kpad) return;
    int n = idx / Kpad;
    int r = idx - n * Kpad;
    float v = 0.f;
    if (r < 3 * Fw) {
        int kb = r / Fw, f = r - kb * Fw;
        v = src[((long)f * 3 + kb) * ldsrc + n];
    }
    ush h, l;
    split_bf16(v, h, l);
    dh[idx] = h; dl[idx] = l;
}
__global__ void wsplit_cand(const float* __restrict__ src, int Fi, int Kpad,
                            ush* __restrict__ dh, ush* __restrict__ dl) {
    int idx = blockIdx.x * 256 + threadIdx.x;
    if (idx >= 64 * Kpad) return;
    int n = idx / Kpad;
    int k = idx - n * Kpad;
    float v = 0.f;
    if (k < 3 * Fi) {
        int kb = k / Fi, f = k - kb * Fi;
        v = src[((long)f * 3 + kb) * 64 + n];
    } else if (k < 3 * Fi + 192) {
        int kp = k - 3 * Fi;
        int kb = kp >> 6, u = kp & 63;
        v = src[((long)(Fi + u) * 3 + kb) * 64 + n];
    }
    ush h, l;
    split_bf16(v, h, l);
    dh[idx] = h; dl[idx] = l;
}
__global__ void wsplit_proj(const float* __restrict__ src,
                            ush* __restrict__ dh, ush* __restrict__ dl) {
    int idx = blockIdx.x * 256 + threadIdx.x;
    if (idx >= 256 * 64) return;
    int n = idx >> 6, k = idx & 63;
    float v = (n < 200) ? src[k * 200 + n] : 0.f;
    ush h, l;
    split_bf16(v, h, l);
    dh[idx] = h; dl[idx] = l;
}

#define ALD 24
#define BLD 24
#define BLDN 72   // diffmma trans-B row width (16B-pad, conflict-free)

// ---------------- mma diffusion kernel (8 warps, trans-B) ----------------
__global__ __launch_bounds__(256) void diffmma(
    const ush* __restrict__ SSh, const ush* __restrict__ SSl,
    const ush* __restrict__ X0h, const ush* __restrict__ X0l, int ldx,
    ush* __restrict__ X1h, ush* __restrict__ X1l,
    ush* __restrict__ X2h, ush* __restrict__ X2l)
{
    __shared__ __align__(16) ush Ah[2][128][ALD], Al[2][128][ALD];
    __shared__ __align__(16) ush Bh[2][16][BLDN], Bl[2][16][BLDN];  // [k][n]
    int tid = threadIdx.x, wid = tid >> 5, lane = tid & 31;
    int wm = wid >> 1, wn = wid & 1;
    int m0 = blockIdx.y * 128, n0 = blockIdx.x * 64;

    float acc[2][4][4];
#pragma unroll
    for (int i = 0; i < 2; i++)
#pragma unroll
        for (int j = 0; j < 4; j++)
#pragma unroll
            for (int q = 0; q < 4; q++) acc[i][j][q] = 0.f;

    uint32_t sAh = smem_u32(Ah), sAl = smem_u32(Al);
    uint32_t sBh = smem_u32(Bh), sBl = smem_u32(Bl);
    int lr = (lane & 7) + ((lane >> 3) & 1) * 8;
    int lc = (lane >> 4) * 8;
    // trans-B fragment address components: row (k) and col (n)
    int bkrow = ((lane >> 3) & 1) * 8 + (lane & 7);
    int bncol = wn * 32 + ((lane >> 4) & 1) * 8;

    int ar = tid >> 1, ak8 = (tid & 1) * 8;
    int bk = tid >> 4, bn4 = (tid & 15) * 4;

    uint4 rah, ral; uint2 rbh2, rbl2;
    auto fetch = [&](int k0) {
        rah = *reinterpret_cast<const uint4*>(SSh + (long)(m0 + ar) * 208 + k0 + ak8);
        ral = *reinterpret_cast<const uint4*>(SSl + (long)(m0 + ar) * 208 + k0 + ak8);
        int k = k0 + bk;
        if (k < 200) {
            long off = (long)k * ldx + n0 + bn4;
            rbh2 = *reinterpret_cast<const uint2*>(X0h + off);
            rbl2 = *reinterpret_cast<const uint2*>(X0l + off);
        } else {
            rbh2 = make_uint2(0, 0); rbl2 = make_uint2(0, 0);
        }
    };
    auto store = [&](int buf) {
        *reinterpret_cast<uint4*>(&Ah[buf][ar][ak8]) = rah;
        *reinterpret_cast<uint4*>(&Al[buf][ar][ak8]) = ral;
        *reinterpret_cast<uint2*>(&Bh[buf][bk][bn4]) = rbh2;   // native [k][n], vector
        *reinterpret_cast<uint2*>(&Bl[buf][bk][bn4]) = rbl2;
    };

    fetch(0); store(0); __syncthreads();
    const int nk = 13;
    for (int kt = 0; kt < nk; kt++) {
        int cur = kt & 1;
        if (kt + 1 < nk) fetch((kt + 1) * 16);
        uint32_t ah[2][4], al[2][4], bh[4][2], bl[4][2];
#pragma unroll
        for (int mi = 0; mi < 2; mi++) {
            uint32_t off = (uint32_t)(((cur * 128 + wm * 32 + mi * 16 + lr) * ALD + lc) * 2);
            ldm_x4(sAh + off, ah[mi][0], ah[mi][1], ah[mi][2], ah[mi][3]);
            ldm_x4(sAl + off, al[mi][0], al[mi][1], al[mi][2], al[mi][3]);
        }
#pragma unroll
        for (int nf2 = 0; nf2 < 2; nf2++) {
            uint32_t off = (uint32_t)(((cur * 16 + bkrow) * BLDN + bncol + nf2 * 16) * 2);
            ldm_x4t(sBh + off, bh[2*nf2][0], bh[2*nf2][1], bh[2*nf2+1][0], bh[2*nf2+1][1]);
            ldm_x4t(sBl + off, bl[2*nf2][0], bl[2*nf2][1], bl[2*nf2+1][0], bl[2*nf2+1][1]);
        }
#pragma unroll
        for (int mi = 0; mi < 2; mi++)
#pragma unroll
            for (int nf = 0; nf < 4; nf++) {
                mma16816(acc[mi][nf], ah[mi], bh[nf]);
                mma16816(acc[mi][nf], al[mi], bh[nf]);
                mma16816(acc[mi][nf], ah[mi], bl[nf]);
            }
        if (kt + 1 < nk) { store(cur ^ 1); __syncthreads(); }
    }

    int g = lane >> 2, tq = lane & 3;
#pragma unroll
    for (int mi = 0; mi < 2; mi++) {
#pragma unroll
        for (int nf = 0; nf < 4; nf++) {
            int cn = n0 + wn * 32 + nf * 8 + 2 * tq;
#pragma unroll
            for (int e = 0; e < 4; e++) {
                int gm = m0 + wm * 32 + mi * 16 + g + (e >> 1) * 8;
                int cc = cn + (e & 1);
                float v = acc[mi][nf][e];
                ush h, l;
                if (gm < 200) {
                    long p = (long)gm * ldx + cc;
                    split_bf16(v, h, l);
                    X1h[p] = h; X1l[p] = l;
                } else if (gm < 400) {
                    long p = (long)(gm - 200) * ldx + cc;
                    float x0 = us2f(X0h[p]) + us2f(X0l[p]);
                    split_bf16(v - x0, h, l);
                    X2h[p] = h; X2l[p] = l;
                }
            }
        }
    }
}

// ---------------- mma feature GEMM (8 warps, x4 B frags) -----------------
template<int MODE>
__device__ __forceinline__ void epi(float v, int gm, int cn,
    const float* bias, const float* H, const float* Uin,
    float* Of1, float* Of2, ush* Oh, ush* Ol, int t)
{
    if (MODE == 2) {
        float s = 1.f / (1.f + expf(-(v + bias[cn])));
        if (cn < UU) {
            ush h, l;
            split_bf16(s * H[gm * UU + cn], h, l);
            Oh[gm * UU + cn] = h; Ol[gm * UU + cn] = l;
        } else {
            Of1[gm * UU + cn - UU] = s;
        }
    } else if (MODE == 3) {
        float c = tanhf(v + bias[cn]);
        float u = Uin[gm * UU + cn];
        float hn = u * H[gm * UU + cn] + (1.f - u) * c;
        Of1[gm * UU + cn] = hn;
        if (Oh) {
            ush h, l;
            split_bf16(hn, h, l);
            Oh[gm * UU + cn] = h; Ol[gm * UU + cn] = l;
        }
    } else if (MODE == 4) {
        if (cn < 200) {
            float p = v + bias[cn];
            int b_ = gm & 63, n_ = gm >> 6;
            Of1[((long)b_ * TT + t) * 40000 + (long)n_ * 200 + cn] = p;
            Of2[(long)b_ * 40000 + (long)n_ * 200 + cn] = p;
        }
    }
}

template<int MODE>
__global__ __launch_bounds__(256) void featmma(
    const ush* __restrict__ A1h, const ush* __restrict__ A1l,
    int lda1, int Fb1, long ch1, int KA,
    const ush* __restrict__ A2h, const ush* __restrict__ A2l, long ch2,
    int K,
    const ush* __restrict__ Bwh, const ush* __restrict__ Bwl, int Kpad, int Nn,
    const float* __restrict__ bias, const float* __restrict__ H,
    const float* __restrict__ Uin,
    float* __restrict__ Of1, float* __restrict__ Of2,
    ush* __restrict__ Oh, ush* __restrict__ Ol, int t)
{
    __shared__ __align__(16) ush Ah[2][128][ALD], Al[2][128][ALD];
    __shared__ __align__(16) ush Bh[2][64][BLD], Bl[2][64][BLD];
    int tid = threadIdx.x, wid = tid >> 5, lane = tid & 31;
    int wm = wid >> 1, wn = wid & 1;
    int m0 = blockIdx.y * 128, n0 = blockIdx.x * 64;

    float acc[2][4][4];
#pragma unroll
    for (int i = 0; i < 2; i++)
#pragma unroll
        for (int j = 0; j < 4; j++)
#pragma unroll
            for (int q = 0; q < 4; q++) acc[i][j][q] = 0.f;

    uint32_t sAh = smem_u32(Ah), sAl = smem_u32(Al);
    uint32_t sBh = smem_u32(Bh), sBl = smem_u32(Bl);
    int lr = (lane & 7) + ((lane >> 3) & 1) * 8;
    int lc = (lane >> 4) * 8;
    // x4 B fragment address: row (n) and col (k)
    int bnrow = ((lane >> 4) & 1) * 8 + (lane & 7);
    int bkcol = ((lane >> 3) & 1) * 8;

    int ar = tid >> 1, ak8 = (tid & 1) * 8;
    int bn = tid >> 2, bk4 = (tid & 3) * 4;

    uint4 rah, ral; uint2 rbh, rbl;
    auto fetch = [&](int k0) {
        int k8 = k0 + ak8;
        if (k8 < K) {
            long off;
            if (k8 < KA) {
                int kb = k8 / Fb1, krel = k8 - kb * Fb1;
                off = (long)kb * ch1 + (long)(m0 + ar) * lda1 + krel;
                rah = *reinterpret_cast<const uint4*>(A1h + off);
                ral = *reinterpret_cast<const uint4*>(A1l + off);
            } else {
                int kp = k8 - KA;
                int kb = kp >> 6, krel = kp & 63;
                off = (long)kb * ch2 + (long)(m0 + ar) * 64 + krel;
                rah = *reinterpret_cast<const uint4*>(A2h + off);
                ral = *reinterpret_cast<const uint4*>(A2l + off);
            }
        } else {
            rah = make_uint4(0, 0, 0, 0);
            ral = make_uint4(0, 0, 0, 0);
        }
        long boff = (long)(n0 + bn) * Kpad + k0 + bk4;
        rbh = *reinterpret_cast<const uint2*>(Bwh + boff);
        rbl = *reinterpret_cast<const uint2*>(Bwl + boff);
    };
    auto store = [&](int buf) {
        *reinterpret_cast<uint4*>(&Ah[buf][ar][ak8]) = rah;
        *reinterpret_cast<uint4*>(&Al[buf][ar][ak8]) = ral;
        *reinterpret_cast<uint2*>(&Bh[buf][bn][bk4]) = rbh;
        *reinterpret_cast<uint2*>(&Bl[buf][bn][bk4]) = rbl;
    };

    int nk = (K + 15) / 16;
    fetch(0); store(0); __syncthreads();
    for (int kt = 0; kt < nk; kt++) {
        int cur = kt & 1;
        if (kt + 1 < nk) fetch((kt + 1) * 16);
        uint32_t ah[2][4], al[2][4], bh[4][2], bl[4][2];
#pragma unroll
        for (int mi = 0; mi < 2; mi++) {
            uint32_t off = (uint32_t)(((cur * 128 + wm * 32 + mi * 16 + lr) * ALD + lc) * 2);
            ldm_x4(sAh + off, ah[mi][0], ah[mi][1], ah[mi][2], ah[mi][3]);
            ldm_x4(sAl + off, al[mi][0], al[mi][1], al[mi][2], al[mi][3]);
        }
#pragma unroll
        for (int nf2 = 0; nf2 < 2; nf2++) {
            uint32_t off = (uint32_t)(((cur * 64 + wn * 32 + nf2 * 16 + bnrow) * BLD + bkcol) * 2);
            ldm_x4(sBh + off, bh[2*nf2][0], bh[2*nf2][1], bh[2*nf2+1][0], bh[2*nf2+1][1]);
            ldm_x4(sBl + off, bl[2*nf2][0], bl[2*nf2][1], bl[2*nf2+1][0], bl[2*nf2+1][1]);
        }
#pragma unroll
        for (int mi = 0; mi < 2; mi++)
#pragma unroll
            for (int nf = 0; nf < 4; nf++) {
                mma16816(acc[mi][nf], ah[mi], bh[nf]);
                mma16816(acc[mi][nf], al[mi], bh[nf]);
                mma16816(acc[mi][nf], ah[mi], bl[nf]);
            }
        if (kt + 1 < nk) { store(cur ^ 1); __syncthreads(); }
    }

    int g = lane >> 2, tq = lane & 3;
#pragma unroll
    for (int mi = 0; mi < 2; mi++)
#pragma unroll
        for (int nf = 0; nf < 4; nf++) {
            int cn = n0 + wn * 32 + nf * 8 + 2 * tq;
#pragma unroll
            for (int e = 0; e < 4; e++) {
                int gm = m0 + wm * 32 + mi * 16 + g + (e >> 1) * 8;
                int cc = cn + (e & 1);
                if (cc < Nn)
                    epi<MODE>(acc[mi][nf][e], gm, cc, bias, H, Uin, Of1, Of2, Oh, Ol, t);
            }
        }
}

// ---------------- host orchestration ----------------
extern "C" void kernel_launch(void* const* d_in, const int* in_sizes, int n_in,
                              void* d_out, int out_size) {
    (void)in_sizes; (void)n_in; (void)out_size;
    const float* inputs  = (const float*)d_in[0];
    const float* Ssup    = (const float*)d_in[1];
    const float* enc_Wg0 = (const float*)d_in[2];
    const float* enc_bg0 = (const float*)d_in[3];
    const float* enc_Wc0 = (const float*)d_in[4];
    const float* enc_bc0 = (const float*)d_in[5];
    const float* enc_Wg  = (const float*)d_in[6];
    const float* enc_bg  = (const float*)d_in[7];
    const float* enc_Wc  = (const float*)d_in[8];
    const float* enc_bc  = (const float*)d_in[9];
    const float* dec_Wg0 = (const float*)d_in[10];
    const float* dec_bg0 = (const float*)d_in[11];
    const float* dec_Wc0 = (const float*)d_in[12];
    const float* dec_bc0 = (const float*)d_in[13];
    const float* dec_Wg  = (const float*)d_in[14];
    const float* dec_bg  = (const float*)d_in[15];
    const float* dec_Wc  = (const float*)d_in[16];
    const float* dec_bc  = (const float*)d_in[17];
    const float* proj_W  = (const float*)d_in[18];
    const float* proj_b  = (const float*)d_in[19];
    float* out = (float*)d_out;

    float *pU, *pH, *pPROJ, *pSS;
    cudaGetSymbolAddress((void**)&pU,    g_U);
    cudaGetSymbolAddress((void**)&pH,    g_H);
    cudaGetSymbolAddress((void**)&pPROJ, g_PROJ);
    cudaGetSymbolAddress((void**)&pSS,   g_SS);
    ush *pXh, *pXl, *pRHh, *pRHl, *ph3h, *ph3l, *pSSh, *pSSl, *pBph, *pBpl;
    cudaGetSymbolAddress((void**)&pXh,  g_Xh);
    cudaGetSymbolAddress((void**)&pXl,  g_Xl);
    cudaGetSymbolAddress((void**)&pRHh, g_RHh);
    cudaGetSymbolAddress((void**)&pRHl, g_RHl);
    cudaGetSymbolAddress((void**)&ph3h, g_h3h);
    cudaGetSymbolAddress((void**)&ph3l, g_h3l);
    cudaGetSymbolAddress((void**)&pSSh, g_SSh);
    cudaGetSymbolAddress((void**)&pSSl, g_SSl);
    cudaGetSymbolAddress((void**)&pBph, g_Bph);
    cudaGetSymbolAddress((void**)&pBpl, g_Bpl);
    ush *pBgh[2], *pBgl[2], *pBch[2], *pBcl[2];
    cudaGetSymbolAddress((void**)&pBgh[0], g_Bgh_e);
    cudaGetSymbolAddress((void**)&pBgl[0], g_Bgl_e);
    cudaGetSymbolAddress((void**)&pBgh[1], g_Bgh_d);
    cudaGetSymbolAddress((void**)&pBgl[1], g_Bgl_d);
    cudaGetSymbolAddress((void**)&pBch[0], g_Bch_e);
    cudaGetSymbolAddress((void**)&pBcl[0], g_Bcl_e);
    cudaGetSymbolAddress((void**)&pBch[1], g_Bch_d);
    cudaGetSymbolAddress((void**)&pBcl[1], g_Bcl_d);

    // ---- prep, launch index 3 == first diffmma (profiled) ----
    s2copy<<<dim3(2, 5), 256>>>(Ssup, pSS);                                  // 0
    ssplit<<<(512 * 208 + 255) / 256, 256>>>(pSS, pSSh, pSSl);               // 1
    build_cat<<<(ROWS * 264) / 256, 256>>>(pXh, pXl, inputs, 0, 0,           // 2
                                           nullptr, 200);
    diffmma<<<dim3(264, 4), 256>>>(pSSh, pSSl, pXh, pXl, 64 * 264,           // 3 <- profiled
        pXh + CHUNK, pXl + CHUNK, pXh + 2 * CHUNK, pXl + 2 * CHUNK);
    zerok<<<(LL * ROWS * UU) / 256, 256>>>(pH, LL * ROWS * UU);              // 4

    // ---- weight splits ----
    const float* Wg0s[2] = {enc_Wg0, dec_Wg0};
    const float* Wgs[2]  = {enc_Wg,  dec_Wg};
    const float* Wc0s[2] = {enc_Wc0, dec_Wc0};
    const float* Wcs[2]  = {enc_Wc,  dec_Wc};
    for (int s = 0; s < 2; s++) {
        wsplitT<<<(128 * 800 + 255) / 256, 256>>>(Wg0s[s], 128, 264, 800, 128,
                                                  pBgh[s], pBgl[s]);
        wsplit_cand<<<(64 * 800 + 255) / 256, 256>>>(Wc0s[s], 200, 800,
                                                     pBch[s], pBcl[s]);
        for (int i = 0; i < 3; i++) {
            wsplitT<<<(128 * 384 + 255) / 256, 256>>>(Wgs[s] + (long)i * 384 * 128, 128,
                128, 384, 128,
                pBgh[s] + 128 * 800 + (long)i * 128 * 384,
                pBgl[s] + 128 * 800 + (long)i * 128 * 384);
            wsplit_cand<<<(64 * 384 + 255) / 256, 256>>>(Wcs[s] + (long)i * 384 * 64, 64, 384,
                pBch[s] + 64 * 800 + (long)i * 64 * 384,
                pBcl[s] + 64 * 800 + (long)i * 64 * 384);
        }
    }
    wsplit_proj<<<64, 256>>>(proj_W, pBph, pBpl);

    ush* RHD1h = pRHh + RHCH; ush* RHD1l = pRHl + RHCH;
    ush* RHD2h = pRHh + 2 * RHCH; ush* RHD2l = pRHl + 2 * RHCH;

    // ---- sequence loop ----
    for (int tg = 0; tg < 2 * TT; tg++) {
        bool enc = (tg < TT);
        int side = enc ? 0 : 1;
        int t = enc ? tg : (tg - TT);

        for (int l = 0; l < LL; l++) {
            int Fi = (l == 0) ? 200 : 64;
            int F = Fi + UU;
            int BF = BB * F;
            float* hl = pH + (long)l * ROWS * UU;

            const ush* Bgh = pBgh[side] + ((l == 0) ? 0 : 128 * 800 + (long)(l - 1) * 128 * 384);
            const ush* Bgl = pBgl[side] + ((l == 0) ? 0 : 128 * 800 + (long)(l - 1) * 128 * 384);
            int Kpg = (l == 0) ? 800 : 384;
            const ush* Bch = pBch[side] + ((l == 0) ? 0 : 64 * 800 + (long)(l - 1) * 64 * 384);
            const ush* Bcl = pBcl[side] + ((l == 0) ? 0 : 64 * 800 + (long)(l - 1) * 64 * 384);
            const float* bg = enc ? ((l == 0) ? enc_bg0 : enc_bg + (l - 1) * 128)
                                  : ((l == 0) ? dec_bg0 : dec_bg + (l - 1) * 128);
            const float* bc = enc ? ((l == 0) ? enc_bc0 : enc_bc + (l - 1) * 64)
                                  : ((l == 0) ? dec_bc0 : dec_bc + (l - 1) * 64);

            int xmode;
            const float* xsrc;
            if (l > 0)       { xmode = 3; xsrc = pH + (long)(l - 1) * ROWS * UU; }
            else if (enc)    { xmode = 0; xsrc = inputs; }
            else if (t == 0) { xmode = 2; xsrc = pPROJ; }
            else             { xmode = 1; xsrc = pPROJ; }

            if (!(tg == 0 && l == 0)) {  // first cell's build+diff issued in prep
                build_cat<<<(ROWS * F) / 256, 256>>>(pXh, pXl, xsrc, xmode, t, hl, Fi);
                diffmma<<<dim3(BF / 64, 4), 256>>>(pSSh, pSSl, pXh, pXl, BF,
                    pXh + CHUNK, pXl + CHUNK, pXh + 2 * CHUNK, pXl + 2 * CHUNK);
            }
            // gates
            featmma<2><<<dim3(2, 100), 256>>>(pXh, pXl, F, F, (long)CHUNK, 3 * F,
                nullptr, nullptr, 0, 3 * F, Bgh, Bgl, Kpg, 128,
                bg, hl, nullptr, pU, nullptr, pRHh, pRHl, 0);
            // rh diffusion
            diffmma<<<dim3(64, 4), 256>>>(pSSh, pSSl, pRHh, pRHl, 4096,
                RHD1h, RHD1l, RHD2h, RHD2l);
            // candidate (fused x + h parts) + GRU update
            featmma<3><<<dim3(1, 100), 256>>>(pXh, pXl, F, Fi, (long)CHUNK, 3 * Fi,
                pRHh, pRHl, (long)RHCH, 3 * Fi + 192, Bch, Bcl, Kpg, 64,
                bc, hl, pU, hl, nullptr,
                (l == 3) ? ph3h : nullptr, (l == 3) ? ph3l : nullptr, 0);
        }

        if (!enc) {
            featmma<4><<<dim3(4, 100), 256>>>(ph3h, ph3l, 64, 64, 0, 64,
                nullptr, nullptr, 0, 64, pBph, pBpl, 64, 200,
                proj_b, nullptr, nullptr, out, pPROJ, nullptr, nullptr, t);
        }
    }
}

// round 17
// speedup vs baseline: 1.9209x; 1.1242x over previous
#include <cuda_runtime.h>
#include <cuda_bf16.h>
#include <math.h>
#include <stdint.h>

// ---------------- problem constants ----------------
#define NN_ 200
#define UU  64
#define BB  64
#define TT  12
#define LL  4
#define ROWS (NN_*BB)        // 12800
#define FMAX 264
#define CHUNK (ROWS*FMAX)
#define RHCH (ROWS*UU)

typedef unsigned short ush;
typedef unsigned int u32;

// ---------------- device scratch ----------------
// activations: interleaved split-bf16, u32 = hi | lo<<16
__device__ u32 g_X[3*CHUNK];          // [x0|x1|x2], ld=F
__device__ u32 g_RH[3*RHCH];          // [rh | S rh | 2S^2 rh - rh]
__device__ u32 g_h3[ROWS*UU];
__device__ float g_U [ROWS*UU];
__device__ float g_H [LL*ROWS*UU];
__device__ float g_PROJ[BB*NN_*NN_];
__device__ float g_SS[400*200];
__device__ ush g_SSh[512*208], g_SSl[512*208];

#define GWSZ (128*800 + 3*128*384)
#define CWSZ (64*800 + 3*64*384)
#define PRSZ (256*64)
__device__ ush g_Bgh_e[GWSZ], g_Bgl_e[GWSZ], g_Bgh_d[GWSZ], g_Bgl_d[GWSZ];
__device__ ush g_Bch_e[CWSZ], g_Bcl_e[CWSZ], g_Bch_d[CWSZ], g_Bcl_d[CWSZ];
__device__ ush g_Bph[PRSZ], g_Bpl[PRSZ];

// ---------------- helpers ----------------
__device__ __forceinline__ uint32_t smem_u32(const void* p) {
    uint32_t a;
    asm("{ .reg .u64 t; cvta.to.shared.u64 t, %1; cvt.u32.u64 %0, t; }" : "=r"(a) : "l"(p));
    return a;
}
__device__ __forceinline__ void ldm_x4(uint32_t a, uint32_t& r0, uint32_t& r1,
                                       uint32_t& r2, uint32_t& r3) {
    asm volatile("ldmatrix.sync.aligned.m8n8.x4.shared.b16 {%0,%1,%2,%3}, [%4];"
                 : "=r"(r0), "=r"(r1), "=r"(r2), "=r"(r3) : "r"(a));
}
__device__ __forceinline__ void ldm_x4t(uint32_t a, uint32_t& r0, uint32_t& r1,
                                        uint32_t& r2, uint32_t& r3) {
    asm volatile("ldmatrix.sync.aligned.m8n8.x4.trans.shared.b16 {%0,%1,%2,%3}, [%4];"
                 : "=r"(r0), "=r"(r1), "=r"(r2), "=r"(r3) : "r"(a));
}
__device__ __forceinline__ void mma16816(float* c, const uint32_t* a, const uint32_t* b) {
    asm volatile("mma.sync.aligned.m16n8k16.row.col.f32.bf16.bf16.f32 "
                 "{%0,%1,%2,%3}, {%4,%5,%6,%7}, {%8,%9}, {%0,%1,%2,%3};"
                 : "+f"(c[0]), "+f"(c[1]), "+f"(c[2]), "+f"(c[3])
                 : "r"(a[0]), "r"(a[1]), "r"(a[2]), "r"(a[3]), "r"(b[0]), "r"(b[1]));
}
__device__ __forceinline__ u32 pack_split(float v) {
    __nv_bfloat16 hb = __float2bfloat16(v);
    float hf = __bfloat162float(hb);
    __nv_bfloat16 lb = __float2bfloat16(v - hf);
    return (u32)__bfloat16_as_ushort(hb) | ((u32)__bfloat16_as_ushort(lb) << 16);
}
__device__ __forceinline__ void split_bf16(float v, ush& h, ush& l) {
    __nv_bfloat16 hb = __float2bfloat16(v);
    float hf = __bfloat162float(hb);
    __nv_bfloat16 lb = __float2bfloat16(v - hf);
    h = __bfloat16_as_ushort(hb);
    l = __bfloat16_as_ushort(lb);
}
__device__ __forceinline__ float us2f(ush u) {
    return __bfloat162float(__ushort_as_bfloat16(u));
}
__device__ __forceinline__ float unpack_f(u32 w) {
    return us2f((ush)(w & 0xffff)) + us2f((ush)(w >> 16));
}

// ---------------- small kernels ----------------
__global__ void zerok(float* p, int n) {
    int i = blockIdx.x * 256 + threadIdx.x;
    if (i < n) p[i] = 0.f;
}

// build X0 = [x | h] interleaved, ld = F. st == nullptr -> h part zero.
__global__ void build_cat(u32* __restrict__ dst,
                          const float* __restrict__ xsrc, int xmode, int t,
                          const float* __restrict__ st, int Fi) {
    int F = Fi + UU;
    int idx = blockIdx.x * 256 + threadIdx.x;
    if (idx >= ROWS * F) return;
    int row = idx / F;
    int f = idx - row * F;
    int n = row >> 6, b = row & 63;
    float v;
    if (f < Fi) {
        if (xmode == 0)      v = xsrc[((long)b * TT + t) * 40000 + (long)n * 200 + f];
        else if (xmode == 1) v = xsrc[(long)b * 40000 + (long)n * 200 + f];
        else if (xmode == 2) v = 0.f;
        else                 v = xsrc[row * UU + f];
    } else {
        v = st ? st[row * UU + (f - Fi)] : 0.f;
    }
    dst[idx] = pack_split(v);
}

// s2copy: out[0:40000) = S (copy), out[40000:80000) = 2*S@S
#define DBK 8
__global__ __launch_bounds__(256) void s2copy(const float* __restrict__ S,
                                              float* __restrict__ out) {
    int cid = blockIdx.y * 2 + blockIdx.x;
    for (int i = threadIdx.x; i < 4000; i += 256)
        out[cid * 4000 + i] = S[cid * 4000 + i];

    __shared__ float As[DBK][40];
    __shared__ float Bs[DBK][128];
    int tid = threadIdx.x;
    int tx = tid & 31, ty = tid >> 5;
    int n0 = blockIdx.x * 128;
    int m0 = blockIdx.y * 40;
    float acc[5][4];
#pragma unroll
    for (int i = 0; i < 5; i++)
#pragma unroll
        for (int j = 0; j < 4; j++) acc[i][j] = 0.f;
    for (int k0 = 0; k0 < 200; k0 += DBK) {
        __syncthreads();
        As[tid & 7][tid >> 3] = S[(m0 + (tid >> 3)) * 200 + k0 + (tid & 7)];
        if (tid < 64) As[tid & 7][(256 + tid) >> 3] = S[(m0 + ((256 + tid) >> 3)) * 200 + k0 + (tid & 7)];
        float4 b4 = make_float4(0.f, 0.f, 0.f, 0.f);
        int gn = n0 + tx * 4;
        if (gn < 200) {
            const float* p = &S[(k0 + ty) * 200 + gn];
            b4.x = p[0]; b4.y = (gn + 1 < 200) ? p[1] : 0.f;
            b4.z = (gn + 2 < 200) ? p[2] : 0.f; b4.w = (gn + 3 < 200) ? p[3] : 0.f;
        }
        *reinterpret_cast<float4*>(&Bs[ty][tx * 4]) = b4;
        __syncthreads();
#pragma unroll
        for (int kk = 0; kk < DBK; kk++) {
            float a[5], b[4];
#pragma unroll
            for (int i = 0; i < 5; i++) a[i] = As[kk][ty * 5 + i];
#pragma unroll
            for (int j = 0; j < 4; j++) b[j] = Bs[kk][tx * 4 + j];
#pragma unroll
            for (int i = 0; i < 5; i++)
#pragma unroll
                for (int j = 0; j < 4; j++) acc[i][j] += a[i] * b[j];
        }
    }
#pragma unroll
    for (int i = 0; i < 5; i++) {
        int gm = m0 + ty * 5 + i;
#pragma unroll
        for (int j = 0; j < 4; j++) {
            int gn = n0 + tx * 4 + j;
            if (gm < 200 && gn < 200) out[40000 + gm * 200 + gn] = 2.f * acc[i][j];
        }
    }
}

__global__ void ssplit(const float* __restrict__ SS,
                       ush* __restrict__ dh, ush* __restrict__ dl) {
    int idx = blockIdx.x * 256 + threadIdx.x;
    if (idx >= 512 * 208) return;
    int m = idx / 208, k = idx - m * 208;
    float v = (m < 400 && k < 200) ? SS[m * 200 + k] : 0.f;
    ush h, l;
    split_bf16(v, h, l);
    dh[idx] = h; dl[idx] = l;
}

__global__ void wsplitT(const float* __restrict__ src, int ldsrc, int Fw,
                        int Kpad, int Nsrc,
                        ush* __restrict__ dh, ush* __restrict__ dl) {
    int idx = blockIdx.x * 256 + threadIdx.x;
    if (idx >= Nsrc * Kpad) return;
    int n = idx / Kpad;
    int r = idx - n * Kpad;
    float v = 0.f;
    if (r < 3 * Fw) {
        int kb = r / Fw, f = r - kb * Fw;
        v = src[((long)f * 3 + kb) * ldsrc + n];
    }
    ush h, l;
    split_bf16(v, h, l);
    dh[idx] = h; dl[idx] = l;
}
__global__ void wsplit_cand(const float* __restrict__ src, int Fi, int Kpad,
                            ush* __restrict__ dh, ush* __restrict__ dl) {
    int idx = blockIdx.x * 256 + threadIdx.x;
    if (idx >= 64 * Kpad) return;
    int n = idx / Kpad;
    int k = idx - n * Kpad;
    float v = 0.f;
    if (k < 3 * Fi) {
        int kb = k / Fi, f = k - kb * Fi;
        v = src[((long)f * 3 + kb) * 64 + n];
    } else if (k < 3 * Fi + 192) {
        int kp = k - 3 * Fi;
        int kb = kp >> 6, u = kp & 63;
        v = src[((long)(Fi + u) * 3 + kb) * 64 + n];
    }
    ush h, l;
    split_bf16(v, h, l);
    dh[idx] = h; dl[idx] = l;
}
__global__ void wsplit_proj(const float* __restrict__ src,
                            ush* __restrict__ dh, ush* __restrict__ dl) {
    int idx = blockIdx.x * 256 + threadIdx.x;
    if (idx >= 256 * 64) return;
    int n = idx >> 6, k = idx & 63;
    float v = (n < 200) ? src[k * 200 + n] : 0.f;
    ush h, l;
    split_bf16(v, h, l);
    dh[idx] = h; dl[idx] = l;
}

#define ALD 24
#define BLD 24
#define BLDN 72   // diffmma trans-B row width

// ---------------- mma diffusion kernel (8 warps, trans-B, interleaved IO) --
__global__ __launch_bounds__(256) void diffmma(
    const ush* __restrict__ SSh, const ush* __restrict__ SSl,
    const u32* __restrict__ X0, int ldx,
    u32* __restrict__ X1, u32* __restrict__ X2)
{
    __shared__ __align__(16) ush Ah[2][128][ALD], Al[2][128][ALD];
    __shared__ __align__(16) ush Bh[2][16][BLDN], Bl[2][16][BLDN];  // [k][n]
    int tid = threadIdx.x, wid = tid >> 5, lane = tid & 31;
    int wm = wid >> 1, wn = wid & 1;
    int m0 = blockIdx.y * 128, n0 = blockIdx.x * 64;

    float acc[2][4][4];
#pragma unroll
    for (int i = 0; i < 2; i++)
#pragma unroll
        for (int j = 0; j < 4; j++)
#pragma unroll
            for (int q = 0; q < 4; q++) acc[i][j][q] = 0.f;

    uint32_t sAh = smem_u32(Ah), sAl = smem_u32(Al);
    uint32_t sBh = smem_u32(Bh), sBl = smem_u32(Bl);
    int lr = (lane & 7) + ((lane >> 3) & 1) * 8;
    int lc = (lane >> 4) * 8;
    int bkrow = ((lane >> 3) & 1) * 8 + (lane & 7);
    int bncol = wn * 32 + ((lane >> 4) & 1) * 8;

    int ar = tid >> 1, ak8 = (tid & 1) * 8;
    int bk = tid >> 4, bn4 = (tid & 15) * 4;

    uint4 rah, ral, rb4;
    auto fetch = [&](int k0) {
        rah = *reinterpret_cast<const uint4*>(SSh + (long)(m0 + ar) * 208 + k0 + ak8);
        ral = *reinterpret_cast<const uint4*>(SSl + (long)(m0 + ar) * 208 + k0 + ak8);
        int k = k0 + bk;
        rb4 = (k < 200) ? *reinterpret_cast<const uint4*>(X0 + (long)k * ldx + n0 + bn4)
                        : make_uint4(0, 0, 0, 0);
    };
    auto store = [&](int buf) {
        *reinterpret_cast<uint4*>(&Ah[buf][ar][ak8]) = rah;
        *reinterpret_cast<uint4*>(&Al[buf][ar][ak8]) = ral;
        uint2 hv, lv;
        hv.x = __byte_perm(rb4.x, rb4.y, 0x5410);
        hv.y = __byte_perm(rb4.z, rb4.w, 0x5410);
        lv.x = __byte_perm(rb4.x, rb4.y, 0x7632);
        lv.y = __byte_perm(rb4.z, rb4.w, 0x7632);
        *reinterpret_cast<uint2*>(&Bh[buf][bk][bn4]) = hv;
        *reinterpret_cast<uint2*>(&Bl[buf][bk][bn4]) = lv;
    };

    fetch(0); store(0); __syncthreads();
    const int nk = 13;
    for (int kt = 0; kt < nk; kt++) {
        int cur = kt & 1;
        if (kt + 1 < nk) fetch((kt + 1) * 16);
        uint32_t ah[2][4], al[2][4], bh[4][2], bl[4][2];
#pragma unroll
        for (int mi = 0; mi < 2; mi++) {
            uint32_t off = (uint32_t)(((cur * 128 + wm * 32 + mi * 16 + lr) * ALD + lc) * 2);
            ldm_x4(sAh + off, ah[mi][0], ah[mi][1], ah[mi][2], ah[mi][3]);
            ldm_x4(sAl + off, al[mi][0], al[mi][1], al[mi][2], al[mi][3]);
        }
#pragma unroll
        for (int nf2 = 0; nf2 < 2; nf2++) {
            uint32_t off = (uint32_t)(((cur * 16 + bkrow) * BLDN + bncol + nf2 * 16) * 2);
            ldm_x4t(sBh + off, bh[2*nf2][0], bh[2*nf2][1], bh[2*nf2+1][0], bh[2*nf2+1][1]);
            ldm_x4t(sBl + off, bl[2*nf2][0], bl[2*nf2][1], bl[2*nf2+1][0], bl[2*nf2+1][1]);
        }
#pragma unroll
        for (int mi = 0; mi < 2; mi++)
#pragma unroll
            for (int nf = 0; nf < 4; nf++) {
                mma16816(acc[mi][nf], ah[mi], bh[nf]);
                mma16816(acc[mi][nf], al[mi], bh[nf]);
                mma16816(acc[mi][nf], ah[mi], bl[nf]);
            }
        if (kt + 1 < nk) { store(cur ^ 1); __syncthreads(); }
    }

    int g = lane >> 2, tq = lane & 3;
#pragma unroll
    for (int mi = 0; mi < 2; mi++) {
#pragma unroll
        for (int nf = 0; nf < 4; nf++) {
            int cn = n0 + wn * 32 + nf * 8 + 2 * tq;
#pragma unroll
            for (int e = 0; e < 4; e++) {
                int gm = m0 + wm * 32 + mi * 16 + g + (e >> 1) * 8;
                int cc = cn + (e & 1);
                float v = acc[mi][nf][e];
                if (gm < 200) {
                    X1[(long)gm * ldx + cc] = pack_split(v);
                } else if (gm < 400) {
                    long p = (long)(gm - 200) * ldx + cc;
                    X2[p] = pack_split(v - unpack_f(X0[p]));
                }
            }
        }
    }
}

// ---------------- mma feature GEMM (8 warps, interleaved A) --------------
template<int MODE>
__device__ __forceinline__ void epi(float v, int gm, int cn,
    const float* bias, const float* H, const float* Uin,
    float* Of1, float* Of2, u32* Opk, int t)
{
    if (MODE == 2) {
        float s = 1.f / (1.f + expf(-(v + bias[cn])));
        if (cn < UU) Opk[gm * UU + cn] = pack_split(s * H[gm * UU + cn]);
        else         Of1[gm * UU + cn - UU] = s;
    } else if (MODE == 3) {
        float c = tanhf(v + bias[cn]);
        float u = Uin[gm * UU + cn];
        float hn = u * H[gm * UU + cn] + (1.f - u) * c;
        Of1[gm * UU + cn] = hn;
        if (Opk) Opk[gm * UU + cn] = pack_split(hn);
    } else if (MODE == 4) {
        if (cn < 200) {
            float p = v + bias[cn];
            int b_ = gm & 63, n_ = gm >> 6;
            Of1[((long)b_ * TT + t) * 40000 + (long)n_ * 200 + cn] = p;
            Of2[(long)b_ * 40000 + (long)n_ * 200 + cn] = p;
        }
    }
}

template<int MODE>
__global__ __launch_bounds__(256) void featmma(
    const u32* __restrict__ A1, int lda1, int Fb1, long ch1, int KA,
    const u32* __restrict__ A2, long ch2,
    int K,
    const ush* __restrict__ Bwh, const ush* __restrict__ Bwl, int Kpad, int Nn,
    const float* __restrict__ bias, const float* __restrict__ H,
    const float* __restrict__ Uin,
    float* __restrict__ Of1, float* __restrict__ Of2,
    u32* __restrict__ Opk, int t)
{
    __shared__ __align__(16) ush Ah[2][128][ALD], Al[2][128][ALD];
    __shared__ __align__(16) ush Bh[2][64][BLD], Bl[2][64][BLD];
    int tid = threadIdx.x, wid = tid >> 5, lane = tid & 31;
    int wm = wid >> 1, wn = wid & 1;
    int m0 = blockIdx.y * 128, n0 = blockIdx.x * 64;

    float acc[2][4][4];
#pragma unroll
    for (int i = 0; i < 2; i++)
#pragma unroll
        for (int j = 0; j < 4; j++)
#pragma unroll
            for (int q = 0; q < 4; q++) acc[i][j][q] = 0.f;

    uint32_t sAh = smem_u32(Ah), sAl = smem_u32(Al);
    uint32_t sBh = smem_u32(Bh), sBl = smem_u32(Bl);
    int lr = (lane & 7) + ((lane >> 3) & 1) * 8;
    int lc = (lane >> 4) * 8;
    int bnrow = ((lane >> 4) & 1) * 8 + (lane & 7);
    int bkcol = ((lane >> 3) & 1) * 8;

    int ar = tid >> 1, ak8 = (tid & 1) * 8;
    int bn = tid >> 2, bk4 = (tid & 3) * 4;

    uint4 ra0, ra1; uint2 rbh, rbl;
    auto fetch = [&](int k0) {
        int k8 = k0 + ak8;
        if (k8 < K) {
            long off;
            if (k8 < KA) {
                int kb = k8 / Fb1, krel = k8 - kb * Fb1;
                off = (long)kb * ch1 + (long)(m0 + ar) * lda1 + krel;
                ra0 = *reinterpret_cast<const uint4*>(A1 + off);
                ra1 = *reinterpret_cast<const uint4*>(A1 + off + 4);
            } else {
                int kp = k8 - KA;
                int kb = kp >> 6, krel = kp & 63;
                off = (long)kb * ch2 + (long)(m0 + ar) * 64 + krel;
                ra0 = *reinterpret_cast<const uint4*>(A2 + off);
                ra1 = *reinterpret_cast<const uint4*>(A2 + off + 4);
            }
        } else {
            ra0 = make_uint4(0, 0, 0, 0);
            ra1 = make_uint4(0, 0, 0, 0);
        }
        long boff = (long)(n0 + bn) * Kpad + k0 + bk4;
        rbh = *reinterpret_cast<const uint2*>(Bwh + boff);
        rbl = *reinterpret_cast<const uint2*>(Bwl + boff);
    };
    auto store = [&](int buf) {
        uint4 hq, lq;
        hq.x = __byte_perm(ra0.x, ra0.y, 0x5410);
        hq.y = __byte_perm(ra0.z, ra0.w, 0x5410);
        hq.z = __byte_perm(ra1.x, ra1.y, 0x5410);
        hq.w = __byte_perm(ra1.z, ra1.w, 0x5410);
        lq.x = __byte_perm(ra0.x, ra0.y, 0x7632);
        lq.y = __byte_perm(ra0.z, ra0.w, 0x7632);
        lq.z = __byte_perm(ra1.x, ra1.y, 0x7632);
        lq.w = __byte_perm(ra1.z, ra1.w, 0x7632);
        *reinterpret_cast<uint4*>(&Ah[buf][ar][ak8]) = hq;
        *reinterpret_cast<uint4*>(&Al[buf][ar][ak8]) = lq;
        *reinterpret_cast<uint2*>(&Bh[buf][bn][bk4]) = rbh;
        *reinterpret_cast<uint2*>(&Bl[buf][bn][bk4]) = rbl;
    };

    int nk = (K + 15) / 16;
    fetch(0); store(0); __syncthreads();
    for (int kt = 0; kt < nk; kt++) {
        int cur = kt & 1;
        if (kt + 1 < nk) fetch((kt + 1) * 16);
        uint32_t ah[2][4], al[2][4], bh[4][2], bl[4][2];
#pragma unroll
        for (int mi = 0; mi < 2; mi++) {
            uint32_t off = (uint32_t)(((cur * 128 + wm * 32 + mi * 16 + lr) * ALD + lc) * 2);
            ldm_x4(sAh + off, ah[mi][0], ah[mi][1], ah[mi][2], ah[mi][3]);
            ldm_x4(sAl + off, al[mi][0], al[mi][1], al[mi][2], al[mi][3]);
        }
#pragma unroll
        for (int nf2 = 0; nf2 < 2; nf2++) {
            uint32_t off = (uint32_t)(((cur * 64 + wn * 32 + nf2 * 16 + bnrow) * BLD + bkcol) * 2);
            ldm_x4(sBh + off, bh[2*nf2][0], bh[2*nf2][1], bh[2*nf2+1][0], bh[2*nf2+1][1]);
            ldm_x4(sBl + off, bl[2*nf2][0], bl[2*nf2][1], bl[2*nf2+1][0], bl[2*nf2+1][1]);
        }
#pragma unroll
        for (int mi = 0; mi < 2; mi++)
#pragma unroll
            for (int nf = 0; nf < 4; nf++) {
                mma16816(acc[mi][nf], ah[mi], bh[nf]);
                mma16816(acc[mi][nf], al[mi], bh[nf]);
                mma16816(acc[mi][nf], ah[mi], bl[nf]);
            }
        if (kt + 1 < nk) { store(cur ^ 1); __syncthreads(); }
    }

    int g = lane >> 2, tq = lane & 3;
#pragma unroll
    for (int mi = 0; mi < 2; mi++)
#pragma unroll
        for (int nf = 0; nf < 4; nf++) {
            int cn = n0 + wn * 32 + nf * 8 + 2 * tq;
#pragma unroll
            for (int e = 0; e < 4; e++) {
                int gm = m0 + wm * 32 + mi * 16 + g + (e >> 1) * 8;
                int cc = cn + (e & 1);
                if (cc < Nn)
                    epi<MODE>(acc[mi][nf][e], gm, cc, bias, H, Uin, Of1, Of2, Opk, t);
            }
        }
}

// ---------------- host orchestration ----------------
extern "C" void kernel_launch(void* const* d_in, const int* in_sizes, int n_in,
                              void* d_out, int out_size) {
    (void)in_sizes; (void)n_in; (void)out_size;
    const float* inputs  = (const float*)d_in[0];
    const float* Ssup    = (const float*)d_in[1];
    const float* enc_Wg0 = (const float*)d_in[2];
    const float* enc_bg0 = (const float*)d_in[3];
    const float* enc_Wc0 = (const float*)d_in[4];
    const float* enc_bc0 = (const float*)d_in[5];
    const float* enc_Wg  = (const float*)d_in[6];
    const float* enc_bg  = (const float*)d_in[7];
    const float* enc_Wc  = (const float*)d_in[8];
    const float* enc_bc  = (const float*)d_in[9];
    const float* dec_Wg0 = (const float*)d_in[10];
    const float* dec_bg0 = (const float*)d_in[11];
    const float* dec_Wc0 = (const float*)d_in[12];
    const float* dec_bc0 = (const float*)d_in[13];
    const float* dec_Wg  = (const float*)d_in[14];
    const float* dec_bg  = (const float*)d_in[15];
    const float* dec_Wc  = (const float*)d_in[16];
    const float* dec_bc  = (const float*)d_in[17];
    const float* proj_W  = (const float*)d_in[18];
    const float* proj_b  = (const float*)d_in[19];
    float* out = (float*)d_out;

    float *pU, *pH, *pPROJ, *pSS;
    cudaGetSymbolAddress((void**)&pU,    g_U);
    cudaGetSymbolAddress((void**)&pH,    g_H);
    cudaGetSymbolAddress((void**)&pPROJ, g_PROJ);
    cudaGetSymbolAddress((void**)&pSS,   g_SS);
    u32 *pX, *pRH, *ph3;
    cudaGetSymbolAddress((void**)&pX,  g_X);
    cudaGetSymbolAddress((void**)&pRH, g_RH);
    cudaGetSymbolAddress((void**)&ph3, g_h3);
    ush *pSSh, *pSSl, *pBph, *pBpl;
    cudaGetSymbolAddress((void**)&pSSh, g_SSh);
    cudaGetSymbolAddress((void**)&pSSl, g_SSl);
    cudaGetSymbolAddress((void**)&pBph, g_Bph);
    cudaGetSymbolAddress((void**)&pBpl, g_Bpl);
    ush *pBgh[2], *pBgl[2], *pBch[2], *pBcl[2];
    cudaGetSymbolAddress((void**)&pBgh[0], g_Bgh_e);
    cudaGetSymbolAddress((void**)&pBgl[0], g_Bgl_e);
    cudaGetSymbolAddress((void**)&pBgh[1], g_Bgh_d);
    cudaGetSymbolAddress((void**)&pBgl[1], g_Bgl_d);
    cudaGetSymbolAddress((void**)&pBch[0], g_Bch_e);
    cudaGetSymbolAddress((void**)&pBcl[0], g_Bcl_e);
    cudaGetSymbolAddress((void**)&pBch[1], g_Bch_d);
    cudaGetSymbolAddress((void**)&pBcl[1], g_Bcl_d);

    // ---- prep, launch index 3 == first diffmma (profiled) ----
    s2copy<<<dim3(2, 5), 256>>>(Ssup, pSS);                                  // 0
    ssplit<<<(512 * 208 + 255) / 256, 256>>>(pSS, pSSh, pSSl);               // 1
    build_cat<<<(ROWS * 264) / 256, 256>>>(pX, inputs, 0, 0, nullptr, 200);  // 2
    diffmma<<<dim3(264, 4), 256>>>(pSSh, pSSl, pX, 64 * 264,                 // 3 <- profiled
        pX + CHUNK, pX + 2 * CHUNK);
    zerok<<<(LL * ROWS * UU) / 256, 256>>>(pH, LL * ROWS * UU);              // 4

    // ---- weight splits ----
    const float* Wg0s[2] = {enc_Wg0, dec_Wg0};
    const float* Wgs[2]  = {enc_Wg,  dec_Wg};
    const float* Wc0s[2] = {enc_Wc0, dec_Wc0};
    const float* Wcs[2]  = {enc_Wc,  dec_Wc};
    for (int s = 0; s < 2; s++) {
        wsplitT<<<(128 * 800 + 255) / 256, 256>>>(Wg0s[s], 128, 264, 800, 128,
                                                  pBgh[s], pBgl[s]);
        wsplit_cand<<<(64 * 800 + 255) / 256, 256>>>(Wc0s[s], 200, 800,
                                                     pBch[s], pBcl[s]);
        for (int i = 0; i < 3; i++) {
            wsplitT<<<(128 * 384 + 255) / 256, 256>>>(Wgs[s] + (long)i * 384 * 128, 128,
                128, 384, 128,
                pBgh[s] + 128 * 800 + (long)i * 128 * 384,
                pBgl[s] + 128 * 800 + (long)i * 128 * 384);
            wsplit_cand<<<(64 * 384 + 255) / 256, 256>>>(Wcs[s] + (long)i * 384 * 64, 64, 384,
                pBch[s] + 64 * 800 + (long)i * 64 * 384,
                pBcl[s] + 64 * 800 + (long)i * 64 * 384);
        }
    }
    wsplit_proj<<<64, 256>>>(proj_W, pBph, pBpl);

    u32* RHD1 = pRH + RHCH;
    u32* RHD2 = pRH + 2 * RHCH;

    // ---- sequence loop ----
    for (int tg = 0; tg < 2 * TT; tg++) {
        bool enc = (tg < TT);
        int side = enc ? 0 : 1;
        int t = enc ? tg : (tg - TT);

        for (int l = 0; l < LL; l++) {
            int Fi = (l == 0) ? 200 : 64;
            int F = Fi + UU;
            int BF = BB * F;
            float* hl = pH + (long)l * ROWS * UU;

            const ush* Bgh = pBgh[side] + ((l == 0) ? 0 : 128 * 800 + (long)(l - 1) * 128 * 384);
            const ush* Bgl = pBgl[side] + ((l == 0) ? 0 : 128 * 800 + (long)(l - 1) * 128 * 384);
            int Kpg = (l == 0) ? 800 : 384;
            const ush* Bch = pBch[side] + ((l == 0) ? 0 : 64 * 800 + (long)(l - 1) * 64 * 384);
            const ush* Bcl = pBcl[side] + ((l == 0) ? 0 : 64 * 800 + (long)(l - 1) * 64 * 384);
            const float* bg = enc ? ((l == 0) ? enc_bg0 : enc_bg + (l - 1) * 128)
                                  : ((l == 0) ? dec_bg0 : dec_bg + (l - 1) * 128);
            const float* bc = enc ? ((l == 0) ? enc_bc0 : enc_bc + (l - 1) * 64)
                                  : ((l == 0) ? dec_bc0 : dec_bc + (l - 1) * 64);

            int xmode;
            const float* xsrc;
            if (l > 0)       { xmode = 3; xsrc = pH + (long)(l - 1) * ROWS * UU; }
            else if (enc)    { xmode = 0; xsrc = inputs; }
            else if (t == 0) { xmode = 2; xsrc = pPROJ; }
            else             { xmode = 1; xsrc = pPROJ; }

            if (!(tg == 0 && l == 0)) {
                build_cat<<<(ROWS * F) / 256, 256>>>(pX, xsrc, xmode, t, hl, Fi);
                diffmma<<<dim3(BF / 64, 4), 256>>>(pSSh, pSSl, pX, BF,
                    pX + CHUNK, pX + 2 * CHUNK);
            }
            // gates
            featmma<2><<<dim3(2, 100), 256>>>(pX, F, F, (long)CHUNK, 3 * F,
                nullptr, 0, 3 * F, Bgh, Bgl, Kpg, 128,
                bg, hl, nullptr, pU, nullptr, pRH, 0);
            // rh diffusion
            diffmma<<<dim3(64, 4), 256>>>(pSSh, pSSl, pRH, 4096, RHD1, RHD2);
            // candidate (fused x + h parts) + GRU update
            featmma<3><<<dim3(1, 100), 256>>>(pX, F, Fi, (long)CHUNK, 3 * Fi,
                pRH, (long)RHCH, 3 * Fi + 192, Bch, Bcl, Kpg, 64,
                bc, hl, pU, hl, nullptr,
                (l == 3) ? ph3 : nullptr, 0);
        }

        if (!enc) {
            featmma<4><<<dim3(4, 100), 256>>>(ph3, 64, 64, 0, 64,
                nullptr, 0, 64, pBph, pBpl, 64, 200,
                proj_b, nullptr, nullptr, out, pPROJ, nullptr, t);
        }
    }
}